// round 6
// baseline (speedup 1.0000x reference)
#include <cuda_runtime.h>
#include <math.h>

// DoublePAN, single persistent kernel, round 6.
//  - 64 blocks x 1024 threads (warp-per-row, 32 rows/block): 4x fewer barrier
//    arrivals, grid < #SMs (no multi-CTA spread), tight-poll barrier (no
//    nanosleep).
//  - p = dinv.*h precomputed in deg phase; width-16 gathers use dual-neighbor
//    lane split (2 neighbors/step across the full warp).
// Phases: [edges || GEMM] b0 [deg+lists+p] b1 [spmm16] b2 [l1post] b3
//         [spmm32] b4 [l2post; clear bits]

#define MAXN 2048
#define MAXNW (MAXN / 32)
#define CAP 128
#define NTHR 1024
#define NWARP 32

__device__ __align__(16) unsigned g_bits[2 * MAXN * MAXNW]; // A rows then B rows
__device__ unsigned g_barctr[8];              // monotonic, never reset
__device__ float    g_q [MAXN * 16];          // h1 (unscaled)
__device__ float    g_p [MAXN * 16];          // dinv .* h1
__device__ float    g_t1[MAXN * 32];
__device__ float    g_q2[MAXN * 32];

__device__ __forceinline__ void gbar(int idx, int nb) {
    __threadfence();
    __syncthreads();
    if (threadIdx.x == 0) {
        unsigned t = atomicAdd(&g_barctr[idx], 1u);
        unsigned target = t - (t % (unsigned)nb) + (unsigned)nb;
        while ((int)(*(volatile unsigned*)&g_barctr[idx] - target) < 0) { }
        __threadfence();
    }
    __syncthreads();
}

__device__ __forceinline__ int warp_exscan(int v, int lane) {
    int s = v;
    #pragma unroll
    for (int o = 1; o < 32; o <<= 1) {
        int u = __shfl_up_sync(0xffffffffu, s, o);
        if (lane >= o) s += u;
    }
    return s - v;
}

__global__ void __launch_bounds__(NTHR) k_mega(
    const float* __restrict__ x, const int* __restrict__ ei,
    const float* __restrict__ fw1, const float* __restrict__ w1,
    const float* __restrict__ b1, const float* __restrict__ fw2,
    const float* __restrict__ w2, const float* __restrict__ b2,
    float* __restrict__ out, int N, int E, int F, int nw)
{
    __shared__ __align__(16) float sW[16 * 512];   // W1 [c][f]; aliased as sA
    __shared__ int   sB[NWARP][CAP];               // per-warp CSR list
    __shared__ float sDinv[NWARP];
    __shared__ int   sDeg[NWARP];

    const int tid = threadIdx.x, bid = blockIdx.x;
    const int gtid = bid * NTHR + tid;
    const int wb = tid >> 5, lane = tid & 31;
    const int row = bid * NWARP + wb;      // grid = N/32

    // ---- edges (bits are zero on entry — invariant) ----
    if (gtid < E) {
        int s = ei[gtid], t = ei[E + gtid];
        atomicOr(&g_bits[s * nw + (t >> 5)], 1u << (t & 31));
        atomicOr(&g_bits[(N + t) * nw + (s >> 5)], 1u << (s & 31));
    }

    // ---- GEMM h1 = x @ W1^T + b1 (independent of graph; before bar 0) ----
    {
        for (int e = tid; e < 16 * 512; e += NTHR) sW[e] = w1[e];
        __syncthreads();
        const float4* x4 = (const float4*)(x + (size_t)row * F);
        float4 xv[4];
        #pragma unroll
        for (int i = 0; i < 4; i++) xv[i] = x4[lane + 32 * i];
        const float4* sW4 = (const float4*)sW;
        float acc[16];
        #pragma unroll
        for (int c = 0; c < 16; c++) acc[c] = 0.f;
        #pragma unroll
        for (int c = 0; c < 16; c++) {
            #pragma unroll
            for (int i = 0; i < 4; i++) {
                float4 wv = sW4[c * 128 + lane + 32 * i];
                acc[c] = fmaf(xv[i].x, wv.x, acc[c]);
                acc[c] = fmaf(xv[i].y, wv.y, acc[c]);
                acc[c] = fmaf(xv[i].z, wv.z, acc[c]);
                acc[c] = fmaf(xv[i].w, wv.w, acc[c]);
            }
        }
        float outv = 0.f;
        #pragma unroll
        for (int c = 0; c < 16; c++) {
            float v = acc[c];
            #pragma unroll
            for (int o = 16; o; o >>= 1) v += __shfl_xor_sync(0xffffffffu, v, o);
            if (lane == c) outv = v;
        }
        if (lane < 16) g_q[row * 16 + lane] = outv + b1[lane];
    }
    gbar(0, gridDim.x);

    // ---- deg + lists + p = dinv.*h ----
    {
        int* sA = (int*)sW;                // [NWARP][CAP] aliases sW
        const unsigned* arow = &g_bits[row * nw];
        const unsigned* brow = &g_bits[(size_t)(N + row) * nw];
        int base = lane * 64;

        unsigned a0 = (2 * lane     < nw) ? arow[2 * lane]     : 0u;
        unsigned a1 = (2 * lane + 1 < nw) ? arow[2 * lane + 1] : 0u;
        int tot = __popc(a0) + __popc(a1);
        int off = warp_exscan(tot, lane);
        int degA = __shfl_sync(0xffffffffu, off + tot, 31);
        int pos = off;
        unsigned wt = a0;
        while (wt) { int bb = __ffs(wt) - 1; wt &= wt - 1; if (pos < CAP) sA[wb * CAP + pos] = base + bb; pos++; }
        wt = a1;
        while (wt) { int bb = __ffs(wt) - 1; wt &= wt - 1; if (pos < CAP) sA[wb * CAP + pos] = base + 32 + bb; pos++; }
        if (degA > CAP) degA = CAP;

        unsigned b0 = (2 * lane     < nw) ? brow[2 * lane]     : 0u;
        unsigned b1v = (2 * lane + 1 < nw) ? brow[2 * lane + 1] : 0u;
        int totB = __popc(b0) + __popc(b1v);
        int offB = warp_exscan(totB, lane);
        int degB = __shfl_sync(0xffffffffu, offB + totB, 31);
        int posB = offB;
        wt = b0;
        while (wt) { int bb = __ffs(wt) - 1; wt &= wt - 1; if (posB < CAP) sB[wb][posB] = base + bb; posB++; }
        wt = b1v;
        while (wt) { int bb = __ffs(wt) - 1; wt &= wt - 1; if (posB < CAP) sB[wb][posB] = base + 32 + bb; posB++; }
        if (lane == 0) sDeg[wb] = degB < CAP ? degB : CAP;
        __syncwarp();

        // union: {row} | Arow | OR_{j in Arow} Arow_j  (8-way batches, MLP 16)
        unsigned acc0 = arow[lane];
        unsigned acc1 = arow[lane + 32];
        int wi = row >> 5; unsigned ib = 1u << (row & 31);
        if (lane == wi)           acc0 |= ib;
        else if (lane + 32 == wi) acc1 |= ib;
        int k = 0;
        for (; k + 8 <= degA; k += 8) {
            #pragma unroll
            for (int u = 0; u < 8; u++) {
                const unsigned* r = &g_bits[sA[wb * CAP + k + u] * nw];
                acc0 |= r[lane];
                acc1 |= r[lane + 32];
            }
        }
        for (; k < degA; k++) {
            const unsigned* r = &g_bits[sA[wb * CAP + k] * nw];
            acc0 |= r[lane];
            acc1 |= r[lane + 32];
        }
        int cnt = __popc(acc0) + __popc(acc1);
        cnt = __reduce_add_sync(0xffffffffu, cnt);
        float dv = rsqrtf((float)cnt);
        if (lane == 0) sDinv[wb] = dv;
        if (lane < 16) g_p[row * 16 + lane] = dv * g_q[row * 16 + lane];
    }
    gbar(1, gridDim.x);

    const int half = lane >> 4, ch = lane & 15;

    // ---- spmm16: t1 = B p   (2 neighbors/step across the warp) ----
    {
        int deg = sDeg[wb];
        float acc = 0.f;
        int k = 0;
        for (; k + 8 <= deg; k += 8) {
            int j0 = sB[wb][k     + half], j1 = sB[wb][k + 2 + half];
            int j2 = sB[wb][k + 4 + half], j3 = sB[wb][k + 6 + half];
            acc = acc + g_p[j0*16+ch] + g_p[j1*16+ch] + g_p[j2*16+ch] + g_p[j3*16+ch];
        }
        for (; k + 2 <= deg; k += 2) acc += g_p[sB[wb][k + half]*16+ch];
        if (k < deg && half == 0)    acc += g_p[sB[wb][k]*16+ch];
        acc += __shfl_down_sync(0xffffffffu, acc, 16);
        if (lane < 16) g_t1[row * 16 + lane] = acc;
    }
    gbar(2, gridDim.x);

    // ---- l1post: t2=B t1; h=relu(d*(f0*p... )); q2=d*(h@W2^T+b2) ----
    {
        int deg = sDeg[wb];
        float t2 = 0.f;
        int k = 0;
        for (; k + 8 <= deg; k += 8) {
            int j0 = sB[wb][k     + half], j1 = sB[wb][k + 2 + half];
            int j2 = sB[wb][k + 4 + half], j3 = sB[wb][k + 6 + half];
            t2 = t2 + g_t1[j0*16+ch] + g_t1[j1*16+ch] + g_t1[j2*16+ch] + g_t1[j3*16+ch];
        }
        for (; k + 2 <= deg; k += 2) t2 += g_t1[sB[wb][k + half]*16+ch];
        if (k < deg && half == 0)    t2 += g_t1[sB[wb][k]*16+ch];
        t2 += __shfl_down_sync(0xffffffffu, t2, 16);

        float f0 = fw1[0], f1 = fw1[1], f2 = fw1[2];
        float d = sDinv[wb];
        float h1 = 0.f;
        if (lane < 16) {
            // f0 * (d.*h) = f0 * p[row]
            float r = f0 * g_p[row*16+lane] + f1 * g_t1[row*16+lane] + f2 * t2;
            h1 = fmaxf(d * r, 0.f);
        }
        float acc = b2[lane];
        #pragma unroll
        for (int k2 = 0; k2 < 16; k2++) {
            float hk = __shfl_sync(0xffffffffu, h1, k2);
            acc = fmaf(w2[lane * 16 + k2], hk, acc);
        }
        g_q2[row * 32 + lane] = d * acc;
    }
    gbar(3, gridDim.x);

    // ---- spmm32: t1 = B q2 ----
    {
        int deg = sDeg[wb];
        float acc = 0.f;
        int k = 0;
        for (; k + 8 <= deg; k += 8) {
            int j0 = sB[wb][k],   j1 = sB[wb][k+1], j2 = sB[wb][k+2], j3 = sB[wb][k+3];
            int j4 = sB[wb][k+4], j5 = sB[wb][k+5], j6 = sB[wb][k+6], j7 = sB[wb][k+7];
            acc = acc + g_q2[j0*32+lane] + g_q2[j1*32+lane] + g_q2[j2*32+lane]
                      + g_q2[j3*32+lane] + g_q2[j4*32+lane] + g_q2[j5*32+lane]
                      + g_q2[j6*32+lane] + g_q2[j7*32+lane];
        }
        for (; k < deg; k++) acc += g_q2[sB[wb][k]*32+lane];
        g_t1[row * 32 + lane] = acc;
    }
    gbar(4, gridDim.x);

    // ---- l2post: t2=B t1; z=d*(f0*q2+f1*t1+f2*t2); log_softmax -> out ----
    {
        int deg = sDeg[wb];
        float t2 = 0.f;
        int k = 0;
        for (; k + 8 <= deg; k += 8) {
            int j0 = sB[wb][k],   j1 = sB[wb][k+1], j2 = sB[wb][k+2], j3 = sB[wb][k+3];
            int j4 = sB[wb][k+4], j5 = sB[wb][k+5], j6 = sB[wb][k+6], j7 = sB[wb][k+7];
            t2 = t2 + g_t1[j0*32+lane] + g_t1[j1*32+lane] + g_t1[j2*32+lane]
                    + g_t1[j3*32+lane] + g_t1[j4*32+lane] + g_t1[j5*32+lane]
                    + g_t1[j6*32+lane] + g_t1[j7*32+lane];
        }
        for (; k < deg; k++) t2 += g_t1[sB[wb][k]*32+lane];
        float f0 = fw2[0], f1 = fw2[1], f2 = fw2[2];
        float d = sDinv[wb];
        float z = d * (f0 * g_q2[row*32+lane] + f1 * g_t1[row*32+lane] + f2 * t2);
        float m = z;
        #pragma unroll
        for (int o = 16; o; o >>= 1) m = fmaxf(m, __shfl_xor_sync(0xffffffffu, m, o));
        float e = __expf(z - m);
        float s = e;
        #pragma unroll
        for (int o = 16; o; o >>= 1) s += __shfl_xor_sync(0xffffffffu, s, o);
        out[row * 32 + lane] = z - m - logf(s);
    }

    // ---- restore invariant: zero g_bits for next replay ----
    ((uint4*)g_bits)[gtid] = make_uint4(0u, 0u, 0u, 0u);
}

extern "C" void kernel_launch(void* const* d_in, const int* in_sizes, int n_in,
                              void* d_out, int out_size) {
    const float* x   = (const float*)d_in[0];
    const int*   ei  = (const int*)  d_in[1];
    const float* fw1 = (const float*)d_in[2];
    const float* w1  = (const float*)d_in[3];
    const float* b1  = (const float*)d_in[4];
    const float* fw2 = (const float*)d_in[5];
    const float* w2  = (const float*)d_in[6];
    const float* b2  = (const float*)d_in[7];
    float* out = (float*)d_out;

    int H = in_sizes[4];            // 16
    int F = in_sizes[3] / H;        // 512
    int N = in_sizes[0] / F;        // 2048
    int E = in_sizes[1] / 2;        // 32768
    int nw = (N + 31) / 32;         // 64

    int grid = N / NWARP;           // 64 blocks; 2*N*nw/4 = grid*NTHR uint4
    k_mega<<<grid, NTHR>>>(x, ei, fw1, w1, b1, fw2, w2, b2, out, N, E, F, nw);
}

// round 7
// speedup vs baseline: 1.2580x; 1.2580x over previous
#include <cuda_runtime.h>
#include <math.h>

// DoublePAN, single persistent kernel, round 7.
// Base = round-5 geometry (256 blocks x 256 threads, best measured), plus:
//  - gather batches deepened to 16 neighbors/round (MLP 16): mean deg=16 rows
//    finish in ONE L2 round trip instead of two.
//  - dual-lane width-16 gathers (2 neighbors per step across the warp).
//  - p = dinv.*h precomputed in union phase.
//  - g_bits clear moved off the kernel tail into the spmm16 phase start.
// Phases: [edges || GEMM] b0 [union+p] b1 [clear; spmm16] b2 [l1post] b3
//         [spmm32] b4 [l2post]

#define MAXN 2048
#define MAXNW (MAXN / 32)
#define CAP 128
#define NTHR 256
#define WPB 8

__device__ __align__(16) unsigned g_bits[2 * MAXN * MAXNW]; // A rows then B rows
__device__ unsigned g_barctr[8];              // monotonic, never reset
__device__ float    g_q [MAXN * 16];          // h1 (unscaled)
__device__ float    g_p [MAXN * 16];          // dinv .* h1
__device__ float    g_t1[MAXN * 32];
__device__ float    g_q2[MAXN * 32];

__device__ __forceinline__ void gbar(int idx) {
    __threadfence();
    __syncthreads();
    if (threadIdx.x == 0) {
        unsigned nb = gridDim.x;
        unsigned t = atomicAdd(&g_barctr[idx], 1u);
        unsigned target = t - (t % nb) + nb;
        while ((int)(*(volatile unsigned*)&g_barctr[idx] - target) < 0) { }
        __threadfence();
    }
    __syncthreads();
}

__device__ __forceinline__ int warp_exscan(int v, int lane) {
    int s = v;
    #pragma unroll
    for (int o = 1; o < 32; o <<= 1) {
        int u = __shfl_up_sync(0xffffffffu, s, o);
        if (lane >= o) s += u;
    }
    return s - v;
}

__global__ void __launch_bounds__(NTHR) k_mega(
    const float* __restrict__ x, const int* __restrict__ ei,
    const float* __restrict__ fw1, const float* __restrict__ w1,
    const float* __restrict__ b1, const float* __restrict__ fw2,
    const float* __restrict__ w2, const float* __restrict__ b2,
    float* __restrict__ out, int N, int E, int F, int nw)
{
    __shared__ __align__(16) float sW[16 * 512];   // W1 [c][f]; aliased as sA
    __shared__ int   sB[WPB][CAP];                 // per-warp CSR list
    __shared__ float sDinv[WPB];
    __shared__ int   sDeg[WPB];

    const int tid = threadIdx.x, bid = blockIdx.x;
    const int gtid = bid * NTHR + tid;
    const int wb = tid >> 5, lane = tid & 31;
    const int row = bid * WPB + wb;        // grid = N/8 = 256

    // ---- edges (bits zero on entry — invariant maintained below) ----
    if (gtid < E) {
        int s = ei[gtid], t = ei[E + gtid];
        atomicOr(&g_bits[s * nw + (t >> 5)], 1u << (t & 31));
        atomicOr(&g_bits[(N + t) * nw + (s >> 5)], 1u << (s & 31));
    }

    // ---- GEMM h1 = x @ W1^T + b1 (graph-independent; before bar 0) ----
    {
        for (int e = tid; e < 16 * 512; e += NTHR) sW[e] = w1[e];
        __syncthreads();
        const float4* x4 = (const float4*)(x + (size_t)row * F);
        float4 xv[4];
        #pragma unroll
        for (int i = 0; i < 4; i++) xv[i] = x4[lane + 32 * i];
        const float4* sW4 = (const float4*)sW;
        float acc[16];
        #pragma unroll
        for (int c = 0; c < 16; c++) acc[c] = 0.f;
        #pragma unroll
        for (int c = 0; c < 16; c++) {
            #pragma unroll
            for (int i = 0; i < 4; i++) {
                float4 wv = sW4[c * 128 + lane + 32 * i];
                acc[c] = fmaf(xv[i].x, wv.x, acc[c]);
                acc[c] = fmaf(xv[i].y, wv.y, acc[c]);
                acc[c] = fmaf(xv[i].z, wv.z, acc[c]);
                acc[c] = fmaf(xv[i].w, wv.w, acc[c]);
            }
        }
        float outv = 0.f;
        #pragma unroll
        for (int c = 0; c < 16; c++) {
            float v = acc[c];
            #pragma unroll
            for (int o = 16; o; o >>= 1) v += __shfl_xor_sync(0xffffffffu, v, o);
            if (lane == c) outv = v;
        }
        if (lane < 16) g_q[row * 16 + lane] = outv + b1[lane];
    }
    gbar(0);

    // ---- union: lists, deg, dinv, p = dinv.*h ----
    {
        int* sA = (int*)sW;                // [WPB][CAP] aliases sW
        const unsigned* arow = &g_bits[row * nw];
        const unsigned* brow = &g_bits[(size_t)(N + row) * nw];
        int base = lane * 64;

        unsigned a0 = (2 * lane     < nw) ? arow[2 * lane]     : 0u;
        unsigned a1 = (2 * lane + 1 < nw) ? arow[2 * lane + 1] : 0u;
        int tot = __popc(a0) + __popc(a1);
        int off = warp_exscan(tot, lane);
        int degA = __shfl_sync(0xffffffffu, off + tot, 31);
        int pos = off;
        unsigned wt = a0;
        while (wt) { int bb = __ffs(wt) - 1; wt &= wt - 1; if (pos < CAP) sA[wb * CAP + pos] = base + bb; pos++; }
        wt = a1;
        while (wt) { int bb = __ffs(wt) - 1; wt &= wt - 1; if (pos < CAP) sA[wb * CAP + pos] = base + 32 + bb; pos++; }
        if (degA > CAP) degA = CAP;

        unsigned b0 = (2 * lane     < nw) ? brow[2 * lane]     : 0u;
        unsigned b1v = (2 * lane + 1 < nw) ? brow[2 * lane + 1] : 0u;
        int totB = __popc(b0) + __popc(b1v);
        int offB = warp_exscan(totB, lane);
        int degB = __shfl_sync(0xffffffffu, offB + totB, 31);
        int posB = offB;
        wt = b0;
        while (wt) { int bb = __ffs(wt) - 1; wt &= wt - 1; if (posB < CAP) sB[wb][posB] = base + bb; posB++; }
        wt = b1v;
        while (wt) { int bb = __ffs(wt) - 1; wt &= wt - 1; if (posB < CAP) sB[wb][posB] = base + 32 + bb; posB++; }
        if (lane == 0) sDeg[wb] = degB < CAP ? degB : CAP;
        __syncwarp();

        // union: {row} | Arow | OR_{j in Arow} Arow_j  (8 rows/iter, MLP 16)
        unsigned acc0 = arow[lane];
        unsigned acc1 = arow[lane + 32];
        int wi = row >> 5; unsigned ib = 1u << (row & 31);
        if (lane == wi)           acc0 |= ib;
        else if (lane + 32 == wi) acc1 |= ib;
        int k = 0;
        for (; k + 8 <= degA; k += 8) {
            #pragma unroll
            for (int u = 0; u < 8; u++) {
                const unsigned* r = &g_bits[sA[wb * CAP + k + u] * nw];
                acc0 |= r[lane];
                acc1 |= r[lane + 32];
            }
        }
        for (; k < degA; k++) {
            const unsigned* r = &g_bits[sA[wb * CAP + k] * nw];
            acc0 |= r[lane];
            acc1 |= r[lane + 32];
        }
        int cnt = __popc(acc0) + __popc(acc1);
        cnt = __reduce_add_sync(0xffffffffu, cnt);
        float dv = rsqrtf((float)cnt);
        if (lane == 0) sDinv[wb] = dv;
        if (lane < 16) g_p[row * 16 + lane] = dv * g_q[row * 16 + lane];
    }
    gbar(1);

    // ---- restore invariant early: zero g_bits (last read was union phase;
    //      everyone passed bar 1). Fire-and-forget stores overlap spmm16. ----
    ((uint4*)g_bits)[gtid] = make_uint4(0u, 0u, 0u, 0u);

    const int half = lane >> 4, ch = lane & 15;

    // ---- spmm16: t1 = B p   (2 neighbors/step; 16 neighbors/round) ----
    {
        int deg = sDeg[wb];
        float acc = 0.f;
        int k = 0;
        for (; k + 16 <= deg; k += 16) {
            float a0 = 0.f;
            #pragma unroll
            for (int u = 0; u < 8; u++) {
                int j = sB[wb][k + 2 * u + half];
                a0 += g_p[j * 16 + ch];
            }
            acc += a0;
        }
        for (; k + 2 <= deg; k += 2) acc += g_p[sB[wb][k + half] * 16 + ch];
        if (k < deg && half == 0)    acc += g_p[sB[wb][k] * 16 + ch];
        acc += __shfl_down_sync(0xffffffffu, acc, 16);
        if (lane < 16) g_t1[row * 16 + lane] = acc;
    }
    gbar(2);

    // ---- l1post: t2=B t1; h=relu(d*(f0*p+f1*t1+f2*t2)); q2=d*(h@W2^T+b2)
    {
        int deg = sDeg[wb];
        float t2 = 0.f;
        int k = 0;
        for (; k + 16 <= deg; k += 16) {
            float a0 = 0.f;
            #pragma unroll
            for (int u = 0; u < 8; u++) {
                int j = sB[wb][k + 2 * u + half];
                a0 += g_t1[j * 16 + ch];
            }
            t2 += a0;
        }
        for (; k + 2 <= deg; k += 2) t2 += g_t1[sB[wb][k + half] * 16 + ch];
        if (k < deg && half == 0)    t2 += g_t1[sB[wb][k] * 16 + ch];
        t2 += __shfl_down_sync(0xffffffffu, t2, 16);

        float f0 = fw1[0], f1 = fw1[1], f2 = fw1[2];
        float d = sDinv[wb];
        float h1 = 0.f;
        if (lane < 16) {
            float r = f0 * g_p[row*16+lane] + f1 * g_t1[row*16+lane] + f2 * t2;
            h1 = fmaxf(d * r, 0.f);
        }
        float acc = b2[lane];
        #pragma unroll
        for (int k2 = 0; k2 < 16; k2++) {
            float hk = __shfl_sync(0xffffffffu, h1, k2);
            acc = fmaf(w2[lane * 16 + k2], hk, acc);
        }
        g_q2[row * 32 + lane] = d * acc;
    }
    gbar(3);

    // ---- spmm32: t1 = B q2   (16 neighbors/round, MLP 16) ----
    {
        int deg = sDeg[wb];
        float acc = 0.f;
        int k = 0;
        for (; k + 16 <= deg; k += 16) {
            float a0 = 0.f;
            #pragma unroll
            for (int u = 0; u < 16; u++)
                a0 += g_q2[sB[wb][k + u] * 32 + lane];
            acc += a0;
        }
        for (; k + 8 <= deg; k += 8) {
            float a0 = 0.f;
            #pragma unroll
            for (int u = 0; u < 8; u++)
                a0 += g_q2[sB[wb][k + u] * 32 + lane];
            acc += a0;
        }
        for (; k < deg; k++) acc += g_q2[sB[wb][k] * 32 + lane];
        g_t1[row * 32 + lane] = acc;
    }
    gbar(4);

    // ---- l2post: t2=B t1; z=d*(f0*q2+f1*t1+f2*t2); log_softmax -> out ----
    {
        int deg = sDeg[wb];
        float t2 = 0.f;
        int k = 0;
        for (; k + 16 <= deg; k += 16) {
            float a0 = 0.f;
            #pragma unroll
            for (int u = 0; u < 16; u++)
                a0 += g_t1[sB[wb][k + u] * 32 + lane];
            t2 += a0;
        }
        for (; k + 8 <= deg; k += 8) {
            float a0 = 0.f;
            #pragma unroll
            for (int u = 0; u < 8; u++)
                a0 += g_t1[sB[wb][k + u] * 32 + lane];
            t2 += a0;
        }
        for (; k < deg; k++) t2 += g_t1[sB[wb][k] * 32 + lane];

        float f0 = fw2[0], f1 = fw2[1], f2 = fw2[2];
        float d = sDinv[wb];
        float z = d * (f0 * g_q2[row*32+lane] + f1 * g_t1[row*32+lane] + f2 * t2);
        float m = z;
        #pragma unroll
        for (int o = 16; o; o >>= 1) m = fmaxf(m, __shfl_xor_sync(0xffffffffu, m, o));
        float e = __expf(z - m);
        float s = e;
        #pragma unroll
        for (int o = 16; o; o >>= 1) s += __shfl_xor_sync(0xffffffffu, s, o);
        out[row * 32 + lane] = z - m - logf(s);
    }
}

extern "C" void kernel_launch(void* const* d_in, const int* in_sizes, int n_in,
                              void* d_out, int out_size) {
    const float* x   = (const float*)d_in[0];
    const int*   ei  = (const int*)  d_in[1];
    const float* fw1 = (const float*)d_in[2];
    const float* w1  = (const float*)d_in[3];
    const float* b1  = (const float*)d_in[4];
    const float* fw2 = (const float*)d_in[5];
    const float* w2  = (const float*)d_in[6];
    const float* b2  = (const float*)d_in[7];
    float* out = (float*)d_out;

    int H = in_sizes[4];            // 16
    int F = in_sizes[3] / H;        // 512
    int N = in_sizes[0] / F;        // 2048
    int E = in_sizes[1] / 2;        // 32768
    int nw = (N + 31) / 32;         // 64

    int grid = N / WPB;             // 256 blocks; grid*NTHR = 65536 = 2*N*nw/4
    k_mega<<<grid, NTHR>>>(x, ei, fw1, w1, b1, fw2, w2, b2, out, N, E, F, nw);
}

// round 8
// speedup vs baseline: 1.3404x; 1.0655x over previous
#include <cuda_runtime.h>
#include <math.h>

// DoublePAN, single persistent kernel, round 8 (base = round-7, 256x256).
//  - own-row values (q, p, t1, q2) carried in REGISTERS across barriers:
//    no dependent phase-head reloads; g_q array deleted.
//  - W2 staged transposed in smem ([k][c], conflict-free); l1post GEMV via
//    per-warp smem h broadcast instead of 16-deep shfl+LDG chain.
//  - union phase widened to 16-row batches (1 L2 round at mean degA=16).
//  - fw1/fw2/b2 preloaded into registers in phase 0.
// Phases: [edges || GEMM] b0 [union+p] b1 [clear; spmm16] b2 [l1post] b3
//         [spmm32] b4 [l2post]

#define MAXN 2048
#define MAXNW (MAXN / 32)
#define CAP 128
#define NTHR 256
#define WPB 8

__device__ __align__(16) unsigned g_bits[2 * MAXN * MAXNW]; // A rows then B rows
__device__ unsigned g_barctr[8];              // monotonic, never reset
__device__ float    g_p [MAXN * 16];          // dinv .* h1
__device__ float    g_t1[MAXN * 32];
__device__ float    g_q2[MAXN * 32];

__device__ __forceinline__ void gbar(int idx) {
    __threadfence();
    __syncthreads();
    if (threadIdx.x == 0) {
        unsigned nb = gridDim.x;
        unsigned t = atomicAdd(&g_barctr[idx], 1u);
        unsigned target = t - (t % nb) + nb;
        while ((int)(*(volatile unsigned*)&g_barctr[idx] - target) < 0) { }
        __threadfence();
    }
    __syncthreads();
}

__device__ __forceinline__ int warp_exscan(int v, int lane) {
    int s = v;
    #pragma unroll
    for (int o = 1; o < 32; o <<= 1) {
        int u = __shfl_up_sync(0xffffffffu, s, o);
        if (lane >= o) s += u;
    }
    return s - v;
}

__global__ void __launch_bounds__(NTHR) k_mega(
    const float* __restrict__ x, const int* __restrict__ ei,
    const float* __restrict__ fw1, const float* __restrict__ w1,
    const float* __restrict__ b1, const float* __restrict__ fw2,
    const float* __restrict__ w2, const float* __restrict__ b2,
    float* __restrict__ out, int N, int E, int F, int nw)
{
    __shared__ __align__(16) float sW[16 * 512];   // W1 [c][f]; aliased as sA
    __shared__ int   sB[WPB][CAP];                 // per-warp CSR list
    __shared__ float sW2T[16 * 32];                // W2^T [k][c], conflict-free
    __shared__ float sH[WPB][16];                  // per-warp h1 broadcast

    const int tid = threadIdx.x, bid = blockIdx.x;
    const int gtid = bid * NTHR + tid;
    const int wb = tid >> 5, lane = tid & 31;
    const int row = bid * WPB + wb;        // grid = N/8 = 256

    // ---- phase 0: edges (bits zero on entry) + constant preloads + GEMM ----
    if (gtid < E) {
        int s = ei[gtid], t = ei[E + gtid];
        atomicOr(&g_bits[s * nw + (t >> 5)], 1u << (t & 31));
        atomicOr(&g_bits[(N + t) * nw + (s >> 5)], 1u << (s & 31));
    }

    const float f10 = fw1[0], f11 = fw1[1], f12 = fw1[2];
    const float f20 = fw2[0], f21 = fw2[1], f22 = fw2[2];
    const float b2r = b2[lane];
    // stage W2 transposed: sW2T[k*32+c] = w2[c*16+k]
    for (int e = tid; e < 512; e += NTHR) {
        int c = e >> 4, k = e & 15;
        sW2T[k * 32 + c] = w2[e];
    }

    float qv = 0.f;   // own-row h1 channel (lanes < 16)
    {
        for (int e = tid; e < 16 * 512; e += NTHR) sW[e] = w1[e];
        __syncthreads();
        const float4* x4 = (const float4*)(x + (size_t)row * F);
        float4 xv[4];
        #pragma unroll
        for (int i = 0; i < 4; i++) xv[i] = x4[lane + 32 * i];
        const float4* sW4 = (const float4*)sW;
        float acc[16];
        #pragma unroll
        for (int c = 0; c < 16; c++) acc[c] = 0.f;
        #pragma unroll
        for (int c = 0; c < 16; c++) {
            #pragma unroll
            for (int i = 0; i < 4; i++) {
                float4 wv = sW4[c * 128 + lane + 32 * i];
                acc[c] = fmaf(xv[i].x, wv.x, acc[c]);
                acc[c] = fmaf(xv[i].y, wv.y, acc[c]);
                acc[c] = fmaf(xv[i].z, wv.z, acc[c]);
                acc[c] = fmaf(xv[i].w, wv.w, acc[c]);
            }
        }
        #pragma unroll
        for (int c = 0; c < 16; c++) {
            float v = acc[c];
            #pragma unroll
            for (int o = 16; o; o >>= 1) v += __shfl_xor_sync(0xffffffffu, v, o);
            if (lane == c) qv = v;
        }
        if (lane < 16) qv += b1[lane];
    }
    gbar(0);

    // ---- union: lists, deg, dinv (all-lane reg), p = dinv*q ----
    float dv;          // dinv[row], all lanes
    int   degB;        // B-list length, all lanes
    float pv = 0.f;    // p[row] own channel (lanes < 16)
    {
        int* sA = (int*)sW;                // [WPB][CAP] aliases sW
        const unsigned* arow = &g_bits[row * nw];
        const unsigned* brow = &g_bits[(size_t)(N + row) * nw];
        int base = lane * 64;

        unsigned a0 = arow[2 * lane], a1 = arow[2 * lane + 1];
        int tot = __popc(a0) + __popc(a1);
        int off = warp_exscan(tot, lane);
        int degA = __shfl_sync(0xffffffffu, off + tot, 31);
        int pos = off;
        unsigned wt = a0;
        while (wt) { int bb = __ffs(wt) - 1; wt &= wt - 1; if (pos < CAP) sA[wb * CAP + pos] = base + bb; pos++; }
        wt = a1;
        while (wt) { int bb = __ffs(wt) - 1; wt &= wt - 1; if (pos < CAP) sA[wb * CAP + pos] = base + 32 + bb; pos++; }
        if (degA > CAP) degA = CAP;

        unsigned b0 = brow[2 * lane], b1v = brow[2 * lane + 1];
        int totB = __popc(b0) + __popc(b1v);
        int offB = warp_exscan(totB, lane);
        degB = __shfl_sync(0xffffffffu, offB + totB, 31);
        int posB = offB;
        wt = b0;
        while (wt) { int bb = __ffs(wt) - 1; wt &= wt - 1; if (posB < CAP) sB[wb][posB] = base + bb; posB++; }
        wt = b1v;
        while (wt) { int bb = __ffs(wt) - 1; wt &= wt - 1; if (posB < CAP) sB[wb][posB] = base + 32 + bb; posB++; }
        if (degB > CAP) degB = CAP;
        __syncwarp();

        // union: {row} | Arow | OR_{j in Arow} Arow_j  (16 rows/iter, MLP 32)
        unsigned acc0 = arow[lane];
        unsigned acc1 = arow[lane + 32];
        int wi = row >> 5; unsigned ib = 1u << (row & 31);
        if (lane == wi)           acc0 |= ib;
        else if (lane + 32 == wi) acc1 |= ib;
        int k = 0;
        for (; k + 16 <= degA; k += 16) {
            #pragma unroll
            for (int u = 0; u < 16; u++) {
                const unsigned* r = &g_bits[sA[wb * CAP + k + u] * nw];
                acc0 |= r[lane];
                acc1 |= r[lane + 32];
            }
        }
        for (; k + 4 <= degA; k += 4) {
            #pragma unroll
            for (int u = 0; u < 4; u++) {
                const unsigned* r = &g_bits[sA[wb * CAP + k + u] * nw];
                acc0 |= r[lane];
                acc1 |= r[lane + 32];
            }
        }
        for (; k < degA; k++) {
            const unsigned* r = &g_bits[sA[wb * CAP + k] * nw];
            acc0 |= r[lane];
            acc1 |= r[lane + 32];
        }
        int cnt = __popc(acc0) + __popc(acc1);
        cnt = __reduce_add_sync(0xffffffffu, cnt);
        dv = rsqrtf((float)cnt);
        if (lane < 16) {
            pv = dv * qv;
            g_p[row * 16 + lane] = pv;
        }
    }
    gbar(1);

    // ---- restore invariant early (last g_bits read was the union phase) ----
    ((uint4*)g_bits)[gtid] = make_uint4(0u, 0u, 0u, 0u);

    const int half = lane >> 4, ch = lane & 15;

    // ---- spmm16: t1 = B p  (dual-lane, 16 neighbors/round) ----
    float t1own;   // valid lanes < 16
    {
        float acc = 0.f;
        int k = 0;
        for (; k + 16 <= degB; k += 16) {
            float a0 = 0.f;
            #pragma unroll
            for (int u = 0; u < 8; u++) {
                int j = sB[wb][k + 2 * u + half];
                a0 += g_p[j * 16 + ch];
            }
            acc += a0;
        }
        for (; k + 2 <= degB; k += 2) acc += g_p[sB[wb][k + half] * 16 + ch];
        if (k < degB && half == 0)    acc += g_p[sB[wb][k] * 16 + ch];
        acc += __shfl_down_sync(0xffffffffu, acc, 16);
        t1own = acc;
        if (lane < 16) g_t1[row * 16 + lane] = acc;
    }
    gbar(2);

    // ---- l1post: t2=B t1; h=relu(d*(f0*p+f1*t1+f2*t2)); q2=d*(W2 h + b2) ----
    float q2own;   // full width (lane = out channel)
    {
        float t2 = 0.f;
        int k = 0;
        for (; k + 16 <= degB; k += 16) {
            float a0 = 0.f;
            #pragma unroll
            for (int u = 0; u < 8; u++) {
                int j = sB[wb][k + 2 * u + half];
                a0 += g_t1[j * 16 + ch];
            }
            t2 += a0;
        }
        for (; k + 2 <= degB; k += 2) t2 += g_t1[sB[wb][k + half] * 16 + ch];
        if (k < degB && half == 0)    t2 += g_t1[sB[wb][k] * 16 + ch];
        t2 += __shfl_down_sync(0xffffffffu, t2, 16);

        if (lane < 16) {
            float r = f10 * pv + f11 * t1own + f12 * t2;
            sH[wb][lane] = fmaxf(dv * r, 0.f);
        }
        __syncwarp();
        float acc = b2r;
        #pragma unroll
        for (int k2 = 0; k2 < 16; k2++)
            acc = fmaf(sW2T[k2 * 32 + lane], sH[wb][k2], acc);
        q2own = dv * acc;
        g_q2[row * 32 + lane] = q2own;
    }
    gbar(3);

    // ---- spmm32: t1 = B q2  (16 neighbors/round) ----
    float t132;
    {
        float acc = 0.f;
        int k = 0;
        for (; k + 16 <= degB; k += 16) {
            float a0 = 0.f;
            #pragma unroll
            for (int u = 0; u < 16; u++)
                a0 += g_q2[sB[wb][k + u] * 32 + lane];
            acc += a0;
        }
        for (; k + 4 <= degB; k += 4) {
            float a0 = 0.f;
            #pragma unroll
            for (int u = 0; u < 4; u++)
                a0 += g_q2[sB[wb][k + u] * 32 + lane];
            acc += a0;
        }
        for (; k < degB; k++) acc += g_q2[sB[wb][k] * 32 + lane];
        t132 = acc;
        g_t1[row * 32 + lane] = acc;
    }
    gbar(4);

    // ---- l2post: t2=B t1; z=d*(f0*q2+f1*t1+f2*t2); log_softmax -> out ----
    {
        float t2 = 0.f;
        int k = 0;
        for (; k + 16 <= degB; k += 16) {
            float a0 = 0.f;
            #pragma unroll
            for (int u = 0; u < 16; u++)
                a0 += g_t1[sB[wb][k + u] * 32 + lane];
            t2 += a0;
        }
        for (; k + 4 <= degB; k += 4) {
            float a0 = 0.f;
            #pragma unroll
            for (int u = 0; u < 4; u++)
                a0 += g_t1[sB[wb][k + u] * 32 + lane];
            t2 += a0;
        }
        for (; k < degB; k++) t2 += g_t1[sB[wb][k] * 32 + lane];

        float z = dv * (f20 * q2own + f21 * t132 + f22 * t2);
        float m = z;
        #pragma unroll
        for (int o = 16; o; o >>= 1) m = fmaxf(m, __shfl_xor_sync(0xffffffffu, m, o));
        float e = __expf(z - m);
        float s = e;
        #pragma unroll
        for (int o = 16; o; o >>= 1) s += __shfl_xor_sync(0xffffffffu, s, o);
        out[row * 32 + lane] = z - m - logf(s);
    }
}

extern "C" void kernel_launch(void* const* d_in, const int* in_sizes, int n_in,
                              void* d_out, int out_size) {
    const float* x   = (const float*)d_in[0];
    const int*   ei  = (const int*)  d_in[1];
    const float* fw1 = (const float*)d_in[2];
    const float* w1  = (const float*)d_in[3];
    const float* b1  = (const float*)d_in[4];
    const float* fw2 = (const float*)d_in[5];
    const float* w2  = (const float*)d_in[6];
    const float* b2  = (const float*)d_in[7];
    float* out = (float*)d_out;

    int H = in_sizes[4];            // 16
    int F = in_sizes[3] / H;        // 512
    int N = in_sizes[0] / F;        // 2048
    int E = in_sizes[1] / 2;        // 32768
    int nw = (N + 31) / 32;         // 64

    int grid = N / WPB;             // 256 blocks; grid*NTHR = 2*N*nw/4 uint4
    k_mega<<<grid, NTHR>>>(x, ei, fw1, w1, b1, fw2, w2, b2, out, N, E, F, nw);
}